// round 6
// baseline (speedup 1.0000x reference)
#include <cuda_runtime.h>
#include <mma.h>
using namespace nvcuda;

#define N_NODES 50000
#define N_EDGES 800000
#define N_GRAPHS 512
#define F_IN 128
#define HID 256
#define SCAN_BS 1024
#define NBLK ((N_NODES + SCAN_BS - 1) / SCAN_BS)   // 49

// ---------------- scratch (device globals) ----------------
__device__ int   g_is64;
__device__ int   g_src[N_EDGES];
__device__ int   g_dst[N_EDGES];
__device__ int   g_batch[N_NODES];
__device__ int   g_deg[N_NODES];
__device__ int   g_fill[N_NODES];
__device__ int   g_rowptr[N_NODES + 1];
__device__ int   g_eidx[N_EDGES];
__device__ int   g_blksum[64];
__device__ int   g_blkoff[64];
__device__ float g_dis[N_NODES];
__device__ float g_bufA[(size_t)N_NODES * HID];     // h   (GEMM out, relu'd)
__device__ float g_bufB[(size_t)N_NODES * HID];     // agg (gather out)
__device__ float g_pool[N_GRAPHS * HID];
__device__ float g_cnt[N_GRAPHS];

// ---------------- index dtype detection + normalization ----------------
__global__ void detect_dtype(const unsigned int* __restrict__ raw) {
    if (threadIdx.x == 0) {
        int all_zero = 1;
        for (int i = 0; i < 128; i++)
            if (raw[2 * i + 1] != 0u) { all_zero = 0; break; }
        g_is64 = all_zero;
    }
}

__global__ void convert_edges(const void* __restrict__ raw) {
    int i = blockIdx.x * blockDim.x + threadIdx.x;
    if (i >= N_EDGES) return;
    if (g_is64) {
        const long long* p = (const long long*)raw;
        g_src[i] = (int)p[i];
        g_dst[i] = (int)p[i + N_EDGES];
    } else {
        const int* p = (const int*)raw;
        g_src[i] = p[i];
        g_dst[i] = p[i + N_EDGES];
    }
}

__global__ void convert_batch(const void* __restrict__ raw) {
    int i = blockIdx.x * blockDim.x + threadIdx.x;
    if (i >= N_NODES) return;
    if (g_is64) g_batch[i] = (int)((const long long*)raw)[i];
    else        g_batch[i] = ((const int*)raw)[i];
}

// ---------------- CSR construction ----------------
__global__ void zero_deg_fill() {
    int i = blockIdx.x * blockDim.x + threadIdx.x;
    if (i < N_NODES) { g_deg[i] = 0; g_fill[i] = 0; }
}

__global__ void deg_hist() {
    int i = blockIdx.x * blockDim.x + threadIdx.x;
    if (i < N_EDGES) atomicAdd(&g_deg[g_dst[i]], 1);
}

__global__ void scan_blocks() {
    __shared__ int sh[SCAN_BS];
    int i = blockIdx.x * SCAN_BS + threadIdx.x;
    int v = (i < N_NODES) ? g_deg[i] : 0;
    sh[threadIdx.x] = v;
    __syncthreads();
    for (int off = 1; off < SCAN_BS; off <<= 1) {
        int t = (threadIdx.x >= off) ? sh[threadIdx.x - off] : 0;
        __syncthreads();
        sh[threadIdx.x] += t;
        __syncthreads();
    }
    if (i < N_NODES) g_rowptr[i] = sh[threadIdx.x] - v;
    if (threadIdx.x == SCAN_BS - 1) g_blksum[blockIdx.x] = sh[threadIdx.x];
}

__global__ void scan_sums() {
    __shared__ int sh[64];
    int v = ((int)threadIdx.x < NBLK) ? g_blksum[threadIdx.x] : 0;
    sh[threadIdx.x] = v;
    __syncthreads();
    for (int off = 1; off < 64; off <<= 1) {
        int t = (threadIdx.x >= off) ? sh[threadIdx.x - off] : 0;
        __syncthreads();
        sh[threadIdx.x] += t;
        __syncthreads();
    }
    if ((int)threadIdx.x < NBLK) g_blkoff[threadIdx.x] = sh[threadIdx.x] - v;
    if (threadIdx.x == 0) g_rowptr[N_NODES] = N_EDGES;
}

__global__ void scan_add() {
    int i = blockIdx.x * SCAN_BS + threadIdx.x;
    if (i < N_NODES) g_rowptr[i] += g_blkoff[blockIdx.x];
}

__global__ void deg_fin() {
    int i = blockIdx.x * blockDim.x + threadIdx.x;
    if (i < N_NODES) g_dis[i] = rsqrtf((float)g_deg[i] + 1.f);
}

__global__ void csr_fill() {
    int e = blockIdx.x * blockDim.x + threadIdx.x;
    if (e >= N_EDGES) return;
    int d = g_dst[e];
    int pos = g_rowptr[d] + atomicAdd(&g_fill[d], 1);
    g_eidx[pos] = g_src[e];
}

// ---------------- gather (aggregation BEFORE linear): warp per node ----------------
// g_bufB[i] = dis[i]^2 * h[i] + sum_{s in N(i)} dis[s]*dis[i] * h[s]
// FROM_BUF: read h from g_bufA (device global); else from ext (input x).
template <int DIM, bool FROM_BUF>
__global__ void gcn_gather(const float* __restrict__ ext) {
    int node = (blockIdx.x * blockDim.x + threadIdx.x) >> 5;
    int lane = threadIdx.x & 31;
    if (node >= N_NODES) return;
    const int NV = DIM / 128;     // float4 per lane

    const float* hsrc = FROM_BUF ? (const float*)g_bufA : ext;

    float di = g_dis[node];
    float dd = di * di;
    const float4* hn = (const float4*)(hsrc + (size_t)node * DIM);

    float4 acc[NV];
#pragma unroll
    for (int v = 0; v < NV; v++) {
        float4 a = hn[lane + 32 * v];
        acc[v] = make_float4(a.x * dd, a.y * dd, a.z * dd, a.w * dd);
    }

    int beg = g_rowptr[node], end = g_rowptr[node + 1];
    for (int e = beg; e < end; e++) {
        int s = g_eidx[e];
        float nrm = g_dis[s] * di;
        const float4* hs = (const float4*)(hsrc + (size_t)s * DIM);
#pragma unroll
        for (int v = 0; v < NV; v++) {
            float4 x = hs[lane + 32 * v];
            acc[v].x = fmaf(x.x, nrm, acc[v].x);
            acc[v].y = fmaf(x.y, nrm, acc[v].y);
            acc[v].z = fmaf(x.z, nrm, acc[v].z);
            acc[v].w = fmaf(x.w, nrm, acc[v].w);
        }
    }

    float4* ob = (float4*)(g_bufB + (size_t)node * DIM);
#pragma unroll
    for (int v = 0; v < NV; v++) ob[lane + 32 * v] = acc[v];
}

// ---------------- 3xTF32 tensor-core GEMM with fused bias+ReLU (+pool) ----------------
// g_bufA[M,256] = relu( g_bufB[M,K] @ W[K,256] + bias ) ; POOL: atomicAdd into g_pool.
// Block tile 128x64, 8 warps (4x2), warp tile 32x32 (wmma m16n16k8 tf32).
#define GBM 128
#define GBN 64
#define LDA 20
#define LDB 68
#define LDC 68

template <bool POOL>
__global__ __launch_bounds__(256) void gemm_tf32(const float* __restrict__ W,
                                                 const float* __restrict__ bias,
                                                 int M, int K) {
    // union smem: compute phase (As hi/lo + Bs hi/lo) vs epilogue phase (Cs)
    __shared__ __align__(16) float smem[GBM * LDC];   // 128*68 = 8704 floats (34.8 KB)
    float* As_hi = smem;                               // [128][LDA]
    float* As_lo = smem + GBM * LDA;                   // [128][LDA]
    float* Bs_hi = smem + 2 * GBM * LDA;               // [8][LDB]
    float* Bs_lo = smem + 2 * GBM * LDA + 8 * LDB;     // [8][LDB]
    float* Cs    = smem;                               // [128][LDC] (epilogue)

    const float* A = g_bufB;
    int bm = blockIdx.y * GBM;
    int bn = blockIdx.x * GBN;
    int tid = threadIdx.x;
    int wid = tid >> 5;
    int wm = (wid >> 1) * 32;    // warp m offset 0/32/64/96
    int wn = (wid & 1) * 32;     // warp n offset 0/32

    wmma::fragment<wmma::accumulator, 16, 16, 8, float> acc[2][2];
#pragma unroll
    for (int i = 0; i < 2; i++)
#pragma unroll
        for (int j = 0; j < 2; j++) wmma::fill_fragment(acc[i][j], 0.f);

    for (int k0 = 0; k0 < K; k0 += 8) {
        // load A tile 128x8 (hi/lo split): thread -> one float4
        {
            int r = tid >> 1, kq = (tid & 1) * 4;
            int gr = bm + r;
            float4 v = make_float4(0.f, 0.f, 0.f, 0.f);
            if (gr < M) v = *(const float4*)(A + (size_t)gr * K + k0 + kq);
            float f[4] = {v.x, v.y, v.z, v.w};
#pragma unroll
            for (int q = 0; q < 4; q++) {
                float hi = wmma::__float_to_tf32(f[q]);
                float lo = wmma::__float_to_tf32(f[q] - hi);
                As_hi[r * LDA + kq + q] = hi;
                As_lo[r * LDA + kq + q] = lo;
            }
        }
        // load B tile 8x64 (hi/lo): threads 0..127 -> one float4
        if (tid < 128) {
            int k = tid >> 4, n4 = (tid & 15) * 4;
            float4 v = *(const float4*)(W + (size_t)(k0 + k) * HID + bn + n4);
            float f[4] = {v.x, v.y, v.z, v.w};
#pragma unroll
            for (int q = 0; q < 4; q++) {
                float hi = wmma::__float_to_tf32(f[q]);
                float lo = wmma::__float_to_tf32(f[q] - hi);
                Bs_hi[k * LDB + n4 + q] = hi;
                Bs_lo[k * LDB + n4 + q] = lo;
            }
        }
        __syncthreads();

        wmma::fragment<wmma::matrix_a, 16, 16, 8, wmma::precision::tf32, wmma::row_major> ah[2], al[2];
        wmma::fragment<wmma::matrix_b, 16, 16, 8, wmma::precision::tf32, wmma::row_major> bh[2], bl[2];
#pragma unroll
        for (int i = 0; i < 2; i++) {
            wmma::load_matrix_sync(ah[i], As_hi + (wm + i * 16) * LDA, LDA);
            wmma::load_matrix_sync(al[i], As_lo + (wm + i * 16) * LDA, LDA);
        }
#pragma unroll
        for (int j = 0; j < 2; j++) {
            wmma::load_matrix_sync(bh[j], Bs_hi + wn + j * 16, LDB);
            wmma::load_matrix_sync(bl[j], Bs_lo + wn + j * 16, LDB);
        }
#pragma unroll
        for (int i = 0; i < 2; i++)
#pragma unroll
            for (int j = 0; j < 2; j++) {
                wmma::mma_sync(acc[i][j], ah[i], bh[j], acc[i][j]);
                wmma::mma_sync(acc[i][j], ah[i], bl[j], acc[i][j]);
                wmma::mma_sync(acc[i][j], al[i], bh[j], acc[i][j]);
            }
        __syncthreads();
    }

    // epilogue via smem staging
#pragma unroll
    for (int i = 0; i < 2; i++)
#pragma unroll
        for (int j = 0; j < 2; j++)
            wmma::store_matrix_sync(Cs + (wm + i * 16) * LDC + wn + j * 16,
                                    acc[i][j], LDC, wmma::mem_row_major);
    __syncthreads();

    // write out 128x64 with bias + relu (+pool)
    for (int idx = tid; idx < GBM * (GBN / 4); idx += 256) {
        int r = idx >> 4;             // 0..127
        int c4 = (idx & 15) * 4;      // 0..60
        int gr = bm + r;
        if (gr >= M) continue;
        float4 v;
        v.x = fmaxf(Cs[r * LDC + c4 + 0] + bias[bn + c4 + 0], 0.f);
        v.y = fmaxf(Cs[r * LDC + c4 + 1] + bias[bn + c4 + 1], 0.f);
        v.z = fmaxf(Cs[r * LDC + c4 + 2] + bias[bn + c4 + 2], 0.f);
        v.w = fmaxf(Cs[r * LDC + c4 + 3] + bias[bn + c4 + 3], 0.f);
        if (POOL) {
            float* pp = g_pool + g_batch[gr] * HID + bn + c4;
            atomicAdd(pp + 0, v.x);
            atomicAdd(pp + 1, v.y);
            atomicAdd(pp + 2, v.z);
            atomicAdd(pp + 3, v.w);
        } else {
            *(float4*)(g_bufA + (size_t)gr * HID + bn + c4) = v;
        }
    }
}

// ---------------- pooling tail ----------------
__global__ void zero_pool() {
    int i = blockIdx.x * blockDim.x + threadIdx.x;
    if (i < N_GRAPHS * HID) g_pool[i] = 0.f;
    if (i < N_GRAPHS) g_cnt[i] = 0.f;
}

__global__ void pool_cnt() {
    int i = blockIdx.x * blockDim.x + threadIdx.x;
    if (i < N_NODES) atomicAdd(&g_cnt[g_batch[i]], 1.f);
}

__global__ void pool_div() {
    int i = blockIdx.x * blockDim.x + threadIdx.x;
    if (i < N_GRAPHS * HID) g_pool[i] /= fmaxf(g_cnt[i >> 8], 1.f);
}

// ---------------- fused MLP head ----------------
__global__ void mlp_head(const float* __restrict__ Wm1, const float* __restrict__ bm1,
                         const float* __restrict__ Wm2, const float* __restrict__ bm2,
                         float* __restrict__ out) {
    int g = blockIdx.x;
    int c = threadIdx.x;
    __shared__ float p[HID];
    __shared__ float z[HID];
    p[c] = g_pool[g * HID + c];
    __syncthreads();
    float acc = bm1[c];
#pragma unroll 8
    for (int k = 0; k < HID; k++) acc = fmaf(p[k], Wm1[k * HID + c], acc);
    z[c] = fmaxf(acc, 0.f) * Wm2[c];
    __syncthreads();
    for (int s = 128; s > 0; s >>= 1) {
        if (c < s) z[c] += z[c + s];
        __syncthreads();
    }
    if (c == 0) out[g] = z[0] + bm2[0];
}

// ---------------- launcher ----------------
extern "C" void kernel_launch(void* const* d_in, const int* in_sizes, int n_in,
                              void* d_out, int out_size) {
    const float* x   = (const float*)d_in[0];
    const void*  ei  = d_in[1];
    const void*  bt  = d_in[2];
    const float* W0  = (const float*)d_in[3];
    const float* b0  = (const float*)d_in[4];
    const float* W1  = (const float*)d_in[5];
    const float* b1  = (const float*)d_in[6];
    const float* W2  = (const float*)d_in[7];
    const float* b2  = (const float*)d_in[8];
    const float* Wm1 = (const float*)d_in[9];
    const float* bm1 = (const float*)d_in[10];
    const float* Wm2 = (const float*)d_in[11];
    const float* bm2 = (const float*)d_in[12];
    float* out = (float*)d_out;

    const int nb_nodes = (N_NODES + 255) / 256;
    const int nb_edges = (N_EDGES + 255) / 256;

    // index normalization
    detect_dtype<<<1, 32>>>((const unsigned int*)ei);
    convert_edges<<<nb_edges, 256>>>(ei);
    convert_batch<<<nb_nodes, 256>>>(bt);

    // CSR build + deg_inv_sqrt
    zero_deg_fill<<<nb_nodes, 256>>>();
    deg_hist<<<nb_edges, 256>>>();
    scan_blocks<<<NBLK, SCAN_BS>>>();
    scan_sums<<<1, 64>>>();
    scan_add<<<NBLK, SCAN_BS>>>();
    deg_fin<<<nb_nodes, 256>>>();
    csr_fill<<<nb_edges, 256>>>();

    const int gat_blocks = (N_NODES * 32 + 255) / 256;
    dim3 gemm_grid(HID / GBN, (N_NODES + GBM - 1) / GBM);

    // layer 0: aggregate x (128-dim) then linear+relu
    gcn_gather<F_IN, false><<<gat_blocks, 256>>>(x);
    gemm_tf32<false><<<gemm_grid, 256>>>(W0, b0, N_NODES, F_IN);
    // layer 1
    gcn_gather<HID, true><<<gat_blocks, 256>>>(nullptr);
    gemm_tf32<false><<<gemm_grid, 256>>>(W1, b1, N_NODES, HID);
    // layer 2 + fused pooling
    gcn_gather<HID, true><<<gat_blocks, 256>>>(nullptr);
    zero_pool<<<(N_GRAPHS * HID + 255) / 256, 256>>>();
    pool_cnt<<<nb_nodes, 256>>>();
    gemm_tf32<true><<<gemm_grid, 256>>>(W2, b2, N_NODES, HID);
    pool_div<<<(N_GRAPHS * HID + 255) / 256, 256>>>();

    // MLP head
    mlp_head<<<N_GRAPHS, HID>>>(Wm1, bm1, Wm2, bm2, out);
}

// round 7
// speedup vs baseline: 1.8325x; 1.8325x over previous
#include <cuda_runtime.h>
#include <cuda_bf16.h>
#include <mma.h>
using namespace nvcuda;

#define N_NODES 50000
#define N_EDGES 800000
#define N_GRAPHS 512
#define F_IN 128
#define HID 256
#define M_PAD 50048                 // 391 * 128
#define SCAN_BS 1024
#define NBLK ((N_NODES + SCAN_BS - 1) / SCAN_BS)   // 49

#define W1_OFS (F_IN * HID)               // 32768
#define W2_OFS (W1_OFS + HID * HID)       // 98304
#define W_TOT  (W2_OFS + HID * HID)       // 163840
#define X_TOT  (N_NODES * F_IN)           // 6400000

// ---------------- scratch (device globals, zero-initialized) ----------------
__device__ int   g_src[N_EDGES];
__device__ int   g_dst[N_EDGES];
__device__ int   g_batch[N_NODES];
__device__ int   g_deg[N_NODES];
__device__ int   g_fill[N_NODES];
__device__ int   g_rowptr[N_NODES + 1];
__device__ int   g_eidx[N_EDGES];
__device__ int   g_blksum[64];
__device__ float g_dis[N_NODES];
__device__ __nv_bfloat16 g_xh[(size_t)M_PAD * F_IN];
__device__ __nv_bfloat16 g_xl[(size_t)M_PAD * F_IN];
__device__ __nv_bfloat16 g_wh[W_TOT];
__device__ __nv_bfloat16 g_wl[W_TOT];
__device__ __nv_bfloat16 g_aggh[(size_t)M_PAD * HID];
__device__ __nv_bfloat16 g_aggl[(size_t)M_PAD * HID];
__device__ float g_bufA[(size_t)M_PAD * HID];   // fp32 h (gemm out)
__device__ float g_bufB[(size_t)M_PAD * HID];   // fp32 h (gather0 out)
__device__ float g_pool[N_GRAPHS * HID];
__device__ float g_cnt[N_GRAPHS];

// ---------------- setup: dtype detect + convert edges/batch + split weights & x ----------------
__device__ __forceinline__ void bf16_split(float f, __nv_bfloat16& h, __nv_bfloat16& l) {
    h = __float2bfloat16(f);
    l = __float2bfloat16(f - __bfloat162float(h));
}

__global__ void convert_all(const void* __restrict__ ei, const void* __restrict__ bt,
                            const float* __restrict__ W0, const float* __restrict__ W1,
                            const float* __restrict__ W2, const float* __restrict__ x) {
    int i = blockIdx.x * blockDim.x + threadIdx.x;

    // per-block index dtype detection (only blocks touching edges/batch need it)
    __shared__ int s64;
    if (i - threadIdx.x < N_EDGES) {          // block overlaps edge range
        if (threadIdx.x == 0) {
            const unsigned int* raw = (const unsigned int*)ei;
            int all_zero = 1;
            for (int k = 0; k < 64; k++)
                if (raw[2 * k + 1] != 0u) { all_zero = 0; break; }
            s64 = all_zero;
        }
        __syncthreads();
    }

    if (i < N_EDGES) {
        if (s64) {
            const long long* p = (const long long*)ei;
            g_src[i] = (int)p[i];
            g_dst[i] = (int)p[i + N_EDGES];
        } else {
            const int* p = (const int*)ei;
            g_src[i] = p[i];
            g_dst[i] = p[i + N_EDGES];
        }
    }
    if (i < N_NODES) {
        g_batch[i] = s64 ? (int)((const long long*)bt)[i] : ((const int*)bt)[i];
        g_deg[i] = 0;
        g_fill[i] = 0;
    }
    if (i < W_TOT) {
        float w;
        if (i < W1_OFS)      w = W0[i];
        else if (i < W2_OFS) w = W1[i - W1_OFS];
        else                 w = W2[i - W2_OFS];
        bf16_split(w, g_wh[i], g_wl[i]);
    }
    if (i < X_TOT) bf16_split(x[i], g_xh[i], g_xl[i]);
}

// ---------------- CSR construction ----------------
__global__ void deg_hist() {
    int i = blockIdx.x * blockDim.x + threadIdx.x;
    if (i < N_EDGES) atomicAdd(&g_deg[g_dst[i]], 1);
}

__global__ void scan_blocks() {
    __shared__ int sh[SCAN_BS];
    int i = blockIdx.x * SCAN_BS + threadIdx.x;
    int v = (i < N_NODES) ? g_deg[i] : 0;
    sh[threadIdx.x] = v;
    __syncthreads();
    for (int off = 1; off < SCAN_BS; off <<= 1) {
        int t = (threadIdx.x >= off) ? sh[threadIdx.x - off] : 0;
        __syncthreads();
        sh[threadIdx.x] += t;
        __syncthreads();
    }
    if (i < N_NODES) g_rowptr[i] = sh[threadIdx.x] - v;
    if (threadIdx.x == SCAN_BS - 1) g_blksum[blockIdx.x] = sh[threadIdx.x];
}

// fold cross-block offset + deg_inv_sqrt + rowptr sentinel into one kernel
__global__ void scan_fuse() {
    __shared__ int off;
    if (threadIdx.x == 0) {
        int s = 0;
        for (int b = 0; b < (int)blockIdx.x; b++) s += g_blksum[b];
        off = s;
    }
    __syncthreads();
    int i = blockIdx.x * SCAN_BS + threadIdx.x;
    if (i < N_NODES) {
        g_rowptr[i] += off;
        g_dis[i] = rsqrtf((float)g_deg[i] + 1.f);
    }
    if (i == 0) g_rowptr[N_NODES] = N_EDGES;
}

__global__ void csr_fill() {
    int e = blockIdx.x * blockDim.x + threadIdx.x;
    if (e >= N_EDGES) return;
    int d = g_dst[e];
    int pos = g_rowptr[d] + atomicAdd(&g_fill[d], 1);
    g_eidx[pos] = g_src[e];
}

// ---------------- bf16-split tensor-core GEMM ----------------
// C[M_PAD,256] = A[M_PAD,K] @ W[K,256] (+ bias, relu), A/W as hi+lo bf16 pairs.
// ASEL: 0 -> A = g_xh/g_xl (K=128) ; 1 -> A = g_aggh/g_aggl (K=256).
// Block 128x128, BK=32, 8 warps, warp tile 32x64 (wmma m16n16k16).
#define BM 128
#define BN 128
#define BK 32
#define LDAS 40
#define LDBS 136

template <int ASEL, bool BIASRELU>
__global__ __launch_bounds__(256) void gemm_bf16(int K, int wofs,
                                                 const float* __restrict__ bias) {
    __shared__ __align__(16) __nv_bfloat16 Ash[BM * LDAS];
    __shared__ __align__(16) __nv_bfloat16 Asl[BM * LDAS];
    __shared__ __align__(16) __nv_bfloat16 Bsh[BK * LDBS];
    __shared__ __align__(16) __nv_bfloat16 Bsl[BK * LDBS];
    __shared__ __align__(16) float sbias[16 * LDBS];

    const __nv_bfloat16* Ah = ASEL ? g_aggh : g_xh;
    const __nv_bfloat16* Al = ASEL ? g_aggl : g_xl;
    const __nv_bfloat16* Bh = g_wh + wofs;
    const __nv_bfloat16* Bl = g_wl + wofs;

    int bm = blockIdx.y * BM;
    int bn = blockIdx.x * BN;
    int tid = threadIdx.x;
    int wid = tid >> 5;
    int wm = (wid >> 1) * 32;     // 0/32/64/96
    int wn = (wid & 1) * 64;      // 0/64

    if (BIASRELU) {
        for (int idx = tid; idx < 16 * 128; idx += 256)
            sbias[(idx >> 7) * LDBS + (idx & 127)] = bias[bn + (idx & 127)];
    }

    wmma::fragment<wmma::accumulator, 16, 16, 16, float> acc[2][4];
#pragma unroll
    for (int i = 0; i < 2; i++)
#pragma unroll
        for (int j = 0; j < 4; j++) wmma::fill_fragment(acc[i][j], 0.f);

    for (int k0 = 0; k0 < K; k0 += BK) {
        // A tiles (hi/lo): 128 rows x 32 k -> 512 uint4 per buffer
#pragma unroll
        for (int id = tid; id < 512; id += 256) {
            int r = id >> 2, q = id & 3;
            const uint4* ph = (const uint4*)(Ah + (size_t)(bm + r) * K + k0) + q;
            const uint4* pl = (const uint4*)(Al + (size_t)(bm + r) * K + k0) + q;
            *(uint4*)&Ash[r * LDAS + q * 8] = *ph;
            *(uint4*)&Asl[r * LDAS + q * 8] = *pl;
        }
        // B tiles (hi/lo): 32 k x 128 n -> 512 uint4 per buffer
#pragma unroll
        for (int id = tid; id < 512; id += 256) {
            int kk = id >> 4, q = id & 15;
            const uint4* ph = (const uint4*)(Bh + (size_t)(k0 + kk) * HID + bn) + q;
            const uint4* pl = (const uint4*)(Bl + (size_t)(k0 + kk) * HID + bn) + q;
            *(uint4*)&Bsh[kk * LDBS + q * 8] = *ph;
            *(uint4*)&Bsl[kk * LDBS + q * 8] = *pl;
        }
        __syncthreads();

#pragma unroll
        for (int ks = 0; ks < 2; ks++) {
            wmma::fragment<wmma::matrix_a, 16, 16, 16, __nv_bfloat16, wmma::row_major> ah[2], al[2];
            wmma::fragment<wmma::matrix_b, 16, 16, 16, __nv_bfloat16, wmma::row_major> bh[4], bl[4];
#pragma unroll
            for (int i = 0; i < 2; i++) {
                wmma::load_matrix_sync(ah[i], Ash + (wm + i * 16) * LDAS + ks * 16, LDAS);
                wmma::load_matrix_sync(al[i], Asl + (wm + i * 16) * LDAS + ks * 16, LDAS);
            }
#pragma unroll
            for (int j = 0; j < 4; j++) {
                wmma::load_matrix_sync(bh[j], Bsh + (ks * 16) * LDBS + wn + j * 16, LDBS);
                wmma::load_matrix_sync(bl[j], Bsl + (ks * 16) * LDBS + wn + j * 16, LDBS);
            }
#pragma unroll
            for (int i = 0; i < 2; i++)
#pragma unroll
                for (int j = 0; j < 4; j++) {
                    wmma::mma_sync(acc[i][j], ah[i], bh[j], acc[i][j]);
                    wmma::mma_sync(acc[i][j], ah[i], bl[j], acc[i][j]);
                    wmma::mma_sync(acc[i][j], al[i], bh[j], acc[i][j]);
                }
        }
        __syncthreads();
    }

    // epilogue: bias + relu via layout-matched bias fragment, direct global store
#pragma unroll
    for (int i = 0; i < 2; i++)
#pragma unroll
        for (int j = 0; j < 4; j++) {
            if (BIASRELU) {
                wmma::fragment<wmma::accumulator, 16, 16, 16, float> bf;
                wmma::load_matrix_sync(bf, sbias + wn + j * 16, LDBS, wmma::mem_row_major);
#pragma unroll
                for (int e = 0; e < acc[i][j].num_elements; e++)
                    acc[i][j].x[e] = fmaxf(acc[i][j].x[e] + bf.x[e], 0.f);
            }
            wmma::store_matrix_sync(g_bufA + (size_t)(bm + wm + i * 16) * HID + bn + wn + j * 16,
                                    acc[i][j], HID, wmma::mem_row_major);
        }
}

// ---------------- gather: warp per node, HID=256 ----------------
// agg[i] = dis[i]^2 * h[i] + sum_{s in N(i)} dis[s]*dis[i]*h[s]
// SRC: 1 -> read g_bufA, 2 -> read g_bufB.
// SPLIT=false: out = relu(agg + bias) fp32 -> g_bufB (layer-0 epilogue).
// SPLIT=true : out = agg split to bf16 hi/lo -> g_aggh/g_aggl.
template <int SRC, bool SPLIT>
__global__ void gcn_gather(const float* __restrict__ bias) {
    int node = (blockIdx.x * blockDim.x + threadIdx.x) >> 5;
    int lane = threadIdx.x & 31;
    if (node >= N_NODES) return;

    const float* hsrc = (SRC == 1) ? (const float*)g_bufA : (const float*)g_bufB;

    float di = g_dis[node];
    float dd = di * di;
    const float4* hn = (const float4*)(hsrc + (size_t)node * HID);

    float4 acc[2];
#pragma unroll
    for (int v = 0; v < 2; v++) {
        float4 a = hn[lane + 32 * v];
        acc[v] = make_float4(a.x * dd, a.y * dd, a.z * dd, a.w * dd);
    }

    int beg = g_rowptr[node], end = g_rowptr[node + 1];
    for (int e = beg; e < end; e++) {
        int s = g_eidx[e];
        float nrm = g_dis[s] * di;
        const float4* hs = (const float4*)(hsrc + (size_t)s * HID);
#pragma unroll
        for (int v = 0; v < 2; v++) {
            float4 x = hs[lane + 32 * v];
            acc[v].x = fmaf(x.x, nrm, acc[v].x);
            acc[v].y = fmaf(x.y, nrm, acc[v].y);
            acc[v].z = fmaf(x.z, nrm, acc[v].z);
            acc[v].w = fmaf(x.w, nrm, acc[v].w);
        }
    }

    if (SPLIT) {
#pragma unroll
        for (int v = 0; v < 2; v++) {
            __nv_bfloat162 h01, h23, l01, l23;
            bf16_split(acc[v].x, h01.x, l01.x);
            bf16_split(acc[v].y, h01.y, l01.y);
            bf16_split(acc[v].z, h23.x, l23.x);
            bf16_split(acc[v].w, h23.y, l23.y);
            uint2 uh = make_uint2(*(unsigned*)&h01, *(unsigned*)&h23);
            uint2 ul = make_uint2(*(unsigned*)&l01, *(unsigned*)&l23);
            ((uint2*)(g_aggh + (size_t)node * HID))[lane + 32 * v] = uh;
            ((uint2*)(g_aggl + (size_t)node * HID))[lane + 32 * v] = ul;
        }
    } else {
        const float4* bi = (const float4*)bias;
        float4* ob = (float4*)(g_bufB + (size_t)node * HID);
#pragma unroll
        for (int v = 0; v < 2; v++) {
            float4 b = bi[lane + 32 * v];
            float4 r;
            r.x = fmaxf(acc[v].x + b.x, 0.f);
            r.y = fmaxf(acc[v].y + b.y, 0.f);
            r.z = fmaxf(acc[v].z + b.z, 0.f);
            r.w = fmaxf(acc[v].w + b.w, 0.f);
            ob[lane + 32 * v] = r;
        }
    }
}

// ---------------- pooling ----------------
__global__ void zero_pool() {
    int i = blockIdx.x * blockDim.x + threadIdx.x;
    if (i < N_GRAPHS * HID) g_pool[i] = 0.f;
    if (i < N_GRAPHS) g_cnt[i] = 0.f;
}

__global__ void pool_cnt() {
    int i = blockIdx.x * blockDim.x + threadIdx.x;
    if (i < N_NODES) atomicAdd(&g_cnt[g_batch[i]], 1.f);
}

// batch is sorted: run-length accumulate, flush on id change -> ~30x fewer atomics
__global__ void pool_run() {
    int c = threadIdx.x;            // column 0..255
    int base = blockIdx.x * 32;
    float run = 0.f;
    int cur = -1;
    for (int r = 0; r < 32; r++) {
        int node = base + r;
        if (node >= N_NODES) break;
        int b = g_batch[node];
        if (b != cur) {
            if (cur >= 0) atomicAdd(&g_pool[cur * HID + c], run);
            run = 0.f;
            cur = b;
        }
        run += g_bufA[(size_t)node * HID + c];
    }
    if (cur >= 0) atomicAdd(&g_pool[cur * HID + c], run);
}

__global__ void pool_div() {
    int i = blockIdx.x * blockDim.x + threadIdx.x;
    if (i < N_GRAPHS * HID) g_pool[i] /= fmaxf(g_cnt[i >> 8], 1.f);
}

// ---------------- fused MLP head ----------------
__global__ void mlp_head(const float* __restrict__ Wm1, const float* __restrict__ bm1,
                         const float* __restrict__ Wm2, const float* __restrict__ bm2,
                         float* __restrict__ out) {
    int g = blockIdx.x;
    int c = threadIdx.x;
    __shared__ float p[HID];
    __shared__ float z[HID];
    p[c] = g_pool[g * HID + c];
    __syncthreads();
    float acc = bm1[c];
#pragma unroll 8
    for (int k = 0; k < HID; k++) acc = fmaf(p[k], Wm1[k * HID + c], acc);
    z[c] = fmaxf(acc, 0.f) * Wm2[c];
    __syncthreads();
    for (int s = 128; s > 0; s >>= 1) {
        if (c < s) z[c] += z[c + s];
        __syncthreads();
    }
    if (c == 0) out[g] = z[0] + bm2[0];
}

// ---------------- launcher ----------------
extern "C" void kernel_launch(void* const* d_in, const int* in_sizes, int n_in,
                              void* d_out, int out_size) {
    const float* x   = (const float*)d_in[0];
    const void*  ei  = d_in[1];
    const void*  bt  = d_in[2];
    const float* W0  = (const float*)d_in[3];
    const float* b0  = (const float*)d_in[4];
    const float* W1  = (const float*)d_in[5];
    const float* b1  = (const float*)d_in[6];
    const float* W2  = (const float*)d_in[7];
    const float* b2  = (const float*)d_in[8];
    const float* Wm1 = (const float*)d_in[9];
    const float* bm1 = (const float*)d_in[10];
    const float* Wm2 = (const float*)d_in[11];
    const float* bm2 = (const float*)d_in[12];
    float* out = (float*)d_out;

    const int nb_edges = (N_EDGES + 255) / 256;
    const int cvt_blocks = (X_TOT + 255) / 256;      // covers edges/batch/weights/x
    const int gat_blocks = (N_NODES * 32 + 255) / 256;
    dim3 gemm_grid(HID / BN, M_PAD / BM);            // (2, 391)

    // launch 0: convert + zero + weight/x split (per-block dtype detect)
    convert_all<<<cvt_blocks, 256>>>(ei, bt, W0, W1, W2, x);
    // launch 1-2
    deg_hist<<<nb_edges, 256>>>();
    scan_blocks<<<NBLK, SCAN_BS>>>();
    // launch 3 (profiled): layer-0 GEMM  bufA = x @ W0   (no bias/relu yet)
    gemm_bf16<0, false><<<gemm_grid, 256>>>(F_IN, 0, nullptr);
    // launch 4-5: finish CSR
    scan_fuse<<<NBLK, SCAN_BS>>>();
    csr_fill<<<nb_edges, 256>>>();
    // layer 0 aggregate + bias + relu -> bufB (fp32)
    gcn_gather<1, false><<<gat_blocks, 256>>>(b0);
    // layer 1: gather(bufB) -> agg bf16 ; gemm -> bufA (bias+relu fused)
    gcn_gather<2, true><<<gat_blocks, 256>>>(nullptr);
    gemm_bf16<1, true><<<gemm_grid, 256>>>(HID, W1_OFS, b1);
    // layer 2
    gcn_gather<1, true><<<gat_blocks, 256>>>(nullptr);
    gemm_bf16<1, true><<<gemm_grid, 256>>>(HID, W2_OFS, b2);
    // mean pool (sorted-batch run aggregation)
    zero_pool<<<(N_GRAPHS * HID + 255) / 256, 256>>>();
    pool_cnt<<<(N_NODES + 255) / 256, 256>>>();
    pool_run<<<(N_NODES + 31) / 32, HID>>>();
    pool_div<<<(N_GRAPHS * HID + 255) / 256, 256>>>();
    // MLP head
    mlp_head<<<N_GRAPHS, HID>>>(Wm1, bm1, Wm2, bm2, out);
}

// round 8
// speedup vs baseline: 2.0737x; 1.1316x over previous
#include <cuda_runtime.h>
#include <cuda_bf16.h>
#include <cuda_pipeline.h>
#include <mma.h>
using namespace nvcuda;

#define N_NODES 50000
#define N_EDGES 800000
#define N_GRAPHS 512
#define F_IN 128
#define HID 256
#define M_PAD 50048                 // 391 * 128
#define SCAN_BS 1024
#define NBLK ((N_NODES + SCAN_BS - 1) / SCAN_BS)   // 49

#define W1_OFS (F_IN * HID)               // 32768
#define W2_OFS (W1_OFS + HID * HID)       // 98304
#define W_TOT  (W2_OFS + HID * HID)       // 163840
#define X_TOT  (N_NODES * F_IN)           // 6400000

// ---------------- scratch (device globals, zero-initialized) ----------------
__device__ int   g_src[N_EDGES];
__device__ int   g_dst[N_EDGES];
__device__ int   g_batch[N_NODES];
__device__ int   g_deg[N_NODES];
__device__ int   g_fill[N_NODES];
__device__ int   g_rowptr[N_NODES + 1];
__device__ int   g_eidx[N_EDGES];
__device__ int   g_blksum[64];
__device__ float g_dis[N_NODES];
__device__ __nv_bfloat16 g_xh[(size_t)M_PAD * F_IN];
__device__ __nv_bfloat16 g_xl[(size_t)M_PAD * F_IN];
__device__ __nv_bfloat16 g_wh[W_TOT];
__device__ __nv_bfloat16 g_wl[W_TOT];
__device__ __nv_bfloat16 g_aggh[(size_t)M_PAD * HID];
__device__ __nv_bfloat16 g_aggl[(size_t)M_PAD * HID];
__device__ float g_bufA[(size_t)M_PAD * HID];   // fp32 h (gemm out)
__device__ float g_bufB[(size_t)M_PAD * HID];   // fp32 h (gather0 out)
__device__ float g_pool[N_GRAPHS * HID];
__device__ float g_cnt[N_GRAPHS];

// ---------------- setup ----------------
__device__ __forceinline__ void bf16_split(float f, __nv_bfloat16& h, __nv_bfloat16& l) {
    h = __float2bfloat16(f);
    l = __float2bfloat16(f - __bfloat162float(h));
}

__global__ void convert_all(const void* __restrict__ ei, const void* __restrict__ bt,
                            const float* __restrict__ W0, const float* __restrict__ W1,
                            const float* __restrict__ W2, const float* __restrict__ x) {
    int i = blockIdx.x * blockDim.x + threadIdx.x;
    __shared__ int s64;
    if (i - threadIdx.x < N_EDGES) {
        if (threadIdx.x == 0) {
            const unsigned int* raw = (const unsigned int*)ei;
            int all_zero = 1;
            for (int k = 0; k < 64; k++)
                if (raw[2 * k + 1] != 0u) { all_zero = 0; break; }
            s64 = all_zero;
        }
        __syncthreads();
    }
    if (i < N_EDGES) {
        if (s64) {
            const long long* p = (const long long*)ei;
            g_src[i] = (int)p[i];
            g_dst[i] = (int)p[i + N_EDGES];
        } else {
            const int* p = (const int*)ei;
            g_src[i] = p[i];
            g_dst[i] = p[i + N_EDGES];
        }
    }
    if (i < N_NODES) {
        g_batch[i] = s64 ? (int)((const long long*)bt)[i] : ((const int*)bt)[i];
        g_deg[i] = 0;
        g_fill[i] = 0;
    }
    if (i < W_TOT) {
        float w;
        if (i < W1_OFS)      w = W0[i];
        else if (i < W2_OFS) w = W1[i - W1_OFS];
        else                 w = W2[i - W2_OFS];
        bf16_split(w, g_wh[i], g_wl[i]);
    }
    if (i < X_TOT) bf16_split(x[i], g_xh[i], g_xl[i]);
}

// ---------------- CSR construction ----------------
__global__ void deg_hist() {
    int i = blockIdx.x * blockDim.x + threadIdx.x;
    if (i < N_EDGES) atomicAdd(&g_deg[g_dst[i]], 1);
}

__global__ void scan_blocks() {
    __shared__ int sh[SCAN_BS];
    int i = blockIdx.x * SCAN_BS + threadIdx.x;
    int v = (i < N_NODES) ? g_deg[i] : 0;
    sh[threadIdx.x] = v;
    __syncthreads();
    for (int off = 1; off < SCAN_BS; off <<= 1) {
        int t = (threadIdx.x >= off) ? sh[threadIdx.x - off] : 0;
        __syncthreads();
        sh[threadIdx.x] += t;
        __syncthreads();
    }
    if (i < N_NODES) g_rowptr[i] = sh[threadIdx.x] - v;
    if (threadIdx.x == SCAN_BS - 1) g_blksum[blockIdx.x] = sh[threadIdx.x];
}

__global__ void scan_fuse() {
    __shared__ int off;
    if (threadIdx.x == 0) {
        int s = 0;
        for (int b = 0; b < (int)blockIdx.x; b++) s += g_blksum[b];
        off = s;
    }
    __syncthreads();
    int i = blockIdx.x * SCAN_BS + threadIdx.x;
    if (i < N_NODES) {
        g_rowptr[i] += off;
        g_dis[i] = rsqrtf((float)g_deg[i] + 1.f);
    }
    if (i == 0) g_rowptr[N_NODES] = N_EDGES;
}

__global__ void csr_fill() {
    int e = blockIdx.x * blockDim.x + threadIdx.x;
    if (e >= N_EDGES) return;
    int d = g_dst[e];
    int pos = g_rowptr[d] + atomicAdd(&g_fill[d], 1);
    g_eidx[pos] = g_src[e];
}

// ---------------- bf16-split tensor-core GEMM, 2-stage cp.async pipeline ----------------
// C[M_PAD,256] = A[M_PAD,K] @ W[K,256] (+ bias, relu).
// Block 128x128, BK=32, 8 warps, warp tile 32x64 (wmma m16n16k16), dynamic smem.
#define BM 128
#define BN 128
#define BK 32
#define LDAS 40
#define LDBS 136
#define A_ELE (BM * LDAS)                 // 5120 bf16 per A buffer
#define B_ELE (BK * LDBS)                 // 4352 bf16 per B buffer
#define STAGE_ELE (2 * A_ELE + 2 * B_ELE) // 18944 bf16 per stage
#define GEMM_SMEM (2 * STAGE_ELE * 2 + 16 * LDBS * 4)   // 75776 + 8704 = 84480 B

template <int ASEL, bool BIASRELU>
__global__ __launch_bounds__(256) void gemm_bf16(int K, int wofs,
                                                 const float* __restrict__ bias) {
    extern __shared__ __align__(16) unsigned char dynsmem[];
    __nv_bfloat16* sm = (__nv_bfloat16*)dynsmem;
    float* sbias = (float*)(dynsmem + 2 * STAGE_ELE * 2);

    const __nv_bfloat16* Ah = ASEL ? g_aggh : g_xh;
    const __nv_bfloat16* Al = ASEL ? g_aggl : g_xl;
    const __nv_bfloat16* Bh = g_wh + wofs;
    const __nv_bfloat16* Bl = g_wl + wofs;

    int bm = blockIdx.y * BM;
    int bn = blockIdx.x * BN;
    int tid = threadIdx.x;
    int wid = tid >> 5;
    int wm = (wid >> 1) * 32;     // 0/32/64/96
    int wn = (wid & 1) * 64;      // 0/64

    if (BIASRELU) {
        for (int idx = tid; idx < 16 * 128; idx += 256)
            sbias[(idx >> 7) * LDBS + (idx & 127)] = bias[bn + (idx & 127)];
    }

    // per-thread load coordinates (8 x 16B cp.async per stage)
    int ar0 = tid >> 1, aq0 = (tid & 1) * 8;              // A: 2 uint4 (rows tid>>1, +128? no:)
    // A tile = 128 rows x 32 cols = 512 uint4 ; thread id and id+256
    // id: r = id>>2, q = id&3
    int a_r[2], a_q[2];
#pragma unroll
    for (int t = 0; t < 2; t++) { int id = tid + t * 256; a_r[t] = id >> 2; a_q[t] = id & 3; }
    int b_k[2], b_q[2];
#pragma unroll
    for (int t = 0; t < 2; t++) { int id = tid + t * 256; b_k[t] = id >> 4; b_q[t] = id & 15; }
    (void)ar0; (void)aq0;

    const int niter = K / BK;

    auto issue_stage = [&](int it, int s) {
        __nv_bfloat16* Ash = sm + s * STAGE_ELE;
        __nv_bfloat16* Asl = Ash + A_ELE;
        __nv_bfloat16* Bsh = Asl + A_ELE;
        __nv_bfloat16* Bsl = Bsh + B_ELE;
        int k0 = it * BK;
#pragma unroll
        for (int t = 0; t < 2; t++) {
            int r = a_r[t], q = a_q[t];
            const __nv_bfloat16* sh = Ah + (size_t)(bm + r) * K + k0 + q * 8;
            const __nv_bfloat16* sl = Al + (size_t)(bm + r) * K + k0 + q * 8;
            __pipeline_memcpy_async(&Ash[r * LDAS + q * 8], sh, 16);
            __pipeline_memcpy_async(&Asl[r * LDAS + q * 8], sl, 16);
        }
#pragma unroll
        for (int t = 0; t < 2; t++) {
            int kk = b_k[t], q = b_q[t];
            const __nv_bfloat16* sh = Bh + (size_t)(k0 + kk) * HID + bn + q * 8;
            const __nv_bfloat16* sl = Bl + (size_t)(k0 + kk) * HID + bn + q * 8;
            __pipeline_memcpy_async(&Bsh[kk * LDBS + q * 8], sh, 16);
            __pipeline_memcpy_async(&Bsl[kk * LDBS + q * 8], sl, 16);
        }
        __pipeline_commit();
    };

    wmma::fragment<wmma::accumulator, 16, 16, 16, float> acc[2][4];
#pragma unroll
    for (int i = 0; i < 2; i++)
#pragma unroll
        for (int j = 0; j < 4; j++) wmma::fill_fragment(acc[i][j], 0.f);

    issue_stage(0, 0);

    for (int it = 0; it < niter; it++) {
        if (it + 1 < niter) issue_stage(it + 1, (it + 1) & 1);
        __pipeline_wait_prior((it + 1 < niter) ? 1 : 0);
        __syncthreads();

        __nv_bfloat16* Ash = sm + (it & 1) * STAGE_ELE;
        __nv_bfloat16* Asl = Ash + A_ELE;
        __nv_bfloat16* Bsh = Asl + A_ELE;
        __nv_bfloat16* Bsl = Bsh + B_ELE;

#pragma unroll
        for (int ks = 0; ks < 2; ks++) {
            wmma::fragment<wmma::matrix_a, 16, 16, 16, __nv_bfloat16, wmma::row_major> ah[2], al[2];
            wmma::fragment<wmma::matrix_b, 16, 16, 16, __nv_bfloat16, wmma::row_major> bh[4], bl[4];
#pragma unroll
            for (int i = 0; i < 2; i++) {
                wmma::load_matrix_sync(ah[i], Ash + (wm + i * 16) * LDAS + ks * 16, LDAS);
                wmma::load_matrix_sync(al[i], Asl + (wm + i * 16) * LDAS + ks * 16, LDAS);
            }
#pragma unroll
            for (int j = 0; j < 4; j++) {
                wmma::load_matrix_sync(bh[j], Bsh + (ks * 16) * LDBS + wn + j * 16, LDBS);
                wmma::load_matrix_sync(bl[j], Bsl + (ks * 16) * LDBS + wn + j * 16, LDBS);
            }
#pragma unroll
            for (int i = 0; i < 2; i++)
#pragma unroll
                for (int j = 0; j < 4; j++) {
                    wmma::mma_sync(acc[i][j], ah[i], bh[j], acc[i][j]);
                    wmma::mma_sync(acc[i][j], ah[i], bl[j], acc[i][j]);
                    wmma::mma_sync(acc[i][j], al[i], bh[j], acc[i][j]);
                }
        }
        __syncthreads();
    }

    // epilogue: bias + relu via layout-matched fragment, direct global store
#pragma unroll
    for (int i = 0; i < 2; i++)
#pragma unroll
        for (int j = 0; j < 4; j++) {
            if (BIASRELU) {
                wmma::fragment<wmma::accumulator, 16, 16, 16, float> bf;
                wmma::load_matrix_sync(bf, sbias + wn + j * 16, LDBS, wmma::mem_row_major);
#pragma unroll
                for (int e = 0; e < acc[i][j].num_elements; e++)
                    acc[i][j].x[e] = fmaxf(acc[i][j].x[e] + bf.x[e], 0.f);
            }
            wmma::store_matrix_sync(g_bufA + (size_t)(bm + wm + i * 16) * HID + bn + wn + j * 16,
                                    acc[i][j], HID, wmma::mem_row_major);
        }
}

// ---------------- gather: warp per node ----------------
template <int SRC, bool SPLIT>
__global__ void gcn_gather(const float* __restrict__ bias) {
    int node = (blockIdx.x * blockDim.x + threadIdx.x) >> 5;
    int lane = threadIdx.x & 31;
    if (node >= N_NODES) return;

    const float* hsrc = (SRC == 1) ? (const float*)g_bufA : (const float*)g_bufB;

    float di = g_dis[node];
    float dd = di * di;
    const float4* hn = (const float4*)(hsrc + (size_t)node * HID);

    float4 acc[2];
#pragma unroll
    for (int v = 0; v < 2; v++) {
        float4 a = hn[lane + 32 * v];
        acc[v] = make_float4(a.x * dd, a.y * dd, a.z * dd, a.w * dd);
    }

    int beg = g_rowptr[node], end = g_rowptr[node + 1];
    for (int e = beg; e < end; e++) {
        int s = g_eidx[e];
        float nrm = g_dis[s] * di;
        const float4* hs = (const float4*)(hsrc + (size_t)s * HID);
#pragma unroll
        for (int v = 0; v < 2; v++) {
            float4 x = hs[lane + 32 * v];
            acc[v].x = fmaf(x.x, nrm, acc[v].x);
            acc[v].y = fmaf(x.y, nrm, acc[v].y);
            acc[v].z = fmaf(x.z, nrm, acc[v].z);
            acc[v].w = fmaf(x.w, nrm, acc[v].w);
        }
    }

    if (SPLIT) {
#pragma unroll
        for (int v = 0; v < 2; v++) {
            __nv_bfloat162 h01, h23, l01, l23;
            bf16_split(acc[v].x, h01.x, l01.x);
            bf16_split(acc[v].y, h01.y, l01.y);
            bf16_split(acc[v].z, h23.x, l23.x);
            bf16_split(acc[v].w, h23.y, l23.y);
            uint2 uh = make_uint2(*(unsigned*)&h01, *(unsigned*)&h23);
            uint2 ul = make_uint2(*(unsigned*)&l01, *(unsigned*)&l23);
            ((uint2*)(g_aggh + (size_t)node * HID))[lane + 32 * v] = uh;
            ((uint2*)(g_aggl + (size_t)node * HID))[lane + 32 * v] = ul;
        }
    } else {
        const float4* bi = (const float4*)bias;
        float4* ob = (float4*)(g_bufB + (size_t)node * HID);
#pragma unroll
        for (int v = 0; v < 2; v++) {
            float4 b = bi[lane + 32 * v];
            float4 r;
            r.x = fmaxf(acc[v].x + b.x, 0.f);
            r.y = fmaxf(acc[v].y + b.y, 0.f);
            r.z = fmaxf(acc[v].z + b.z, 0.f);
            r.w = fmaxf(acc[v].w + b.w, 0.f);
            ob[lane + 32 * v] = r;
        }
    }
}

// ---------------- pooling ----------------
__global__ void zero_pool() {
    int i = blockIdx.x * blockDim.x + threadIdx.x;
    if (i < N_GRAPHS * HID) g_pool[i] = 0.f;
    if (i < N_GRAPHS) g_cnt[i] = 0.f;
}

__global__ void pool_cnt() {
    int i = blockIdx.x * blockDim.x + threadIdx.x;
    if (i < N_NODES) atomicAdd(&g_cnt[g_batch[i]], 1.f);
}

__global__ void pool_run() {
    int c = threadIdx.x;
    int base = blockIdx.x * 32;
    float run = 0.f;
    int cur = -1;
    for (int r = 0; r < 32; r++) {
        int node = base + r;
        if (node >= N_NODES) break;
        int b = g_batch[node];
        if (b != cur) {
            if (cur >= 0) atomicAdd(&g_pool[cur * HID + c], run);
            run = 0.f;
            cur = b;
        }
        run += g_bufA[(size_t)node * HID + c];
    }
    if (cur >= 0) atomicAdd(&g_pool[cur * HID + c], run);
}

__global__ void pool_div() {
    int i = blockIdx.x * blockDim.x + threadIdx.x;
    if (i < N_GRAPHS * HID) g_pool[i] /= fmaxf(g_cnt[i >> 8], 1.f);
}

// ---------------- fused MLP head ----------------
__global__ void mlp_head(const float* __restrict__ Wm1, const float* __restrict__ bm1,
                         const float* __restrict__ Wm2, const float* __restrict__ bm2,
                         float* __restrict__ out) {
    int g = blockIdx.x;
    int c = threadIdx.x;
    __shared__ float p[HID];
    __shared__ float z[HID];
    p[c] = g_pool[g * HID + c];
    __syncthreads();
    float acc = bm1[c];
#pragma unroll 8
    for (int k = 0; k < HID; k++) acc = fmaf(p[k], Wm1[k * HID + c], acc);
    z[c] = fmaxf(acc, 0.f) * Wm2[c];
    __syncthreads();
    for (int s = 128; s > 0; s >>= 1) {
        if (c < s) z[c] += z[c + s];
        __syncthreads();
    }
    if (c == 0) out[g] = z[0] + bm2[0];
}

// ---------------- launcher ----------------
extern "C" void kernel_launch(void* const* d_in, const int* in_sizes, int n_in,
                              void* d_out, int out_size) {
    const float* x   = (const float*)d_in[0];
    const void*  ei  = d_in[1];
    const void*  bt  = d_in[2];
    const float* W0  = (const float*)d_in[3];
    const float* b0  = (const float*)d_in[4];
    const float* W1  = (const float*)d_in[5];
    const float* b1  = (const float*)d_in[6];
    const float* W2  = (const float*)d_in[7];
    const float* b2  = (const float*)d_in[8];
    const float* Wm1 = (const float*)d_in[9];
    const float* bm1 = (const float*)d_in[10];
    const float* Wm2 = (const float*)d_in[11];
    const float* bm2 = (const float*)d_in[12];
    float* out = (float*)d_out;

    // allow >48KB dynamic smem (attribute set, not a stream op; capture-safe)
    cudaFuncSetAttribute(gemm_bf16<0, false>, cudaFuncAttributeMaxDynamicSharedMemorySize, GEMM_SMEM);
    cudaFuncSetAttribute(gemm_bf16<1, true>,  cudaFuncAttributeMaxDynamicSharedMemorySize, GEMM_SMEM);

    const int nb_edges = (N_EDGES + 255) / 256;
    const int cvt_blocks = (X_TOT + 255) / 256;
    const int gat_blocks = (N_NODES * 32 + 255) / 256;
    dim3 gemm_grid(HID / BN, M_PAD / BM);            // (2, 391)

    convert_all<<<cvt_blocks, 256>>>(ei, bt, W0, W1, W2, x);
    deg_hist<<<nb_edges, 256>>>();
    scan_blocks<<<NBLK, SCAN_BS>>>();
    // launch 3 (profiled): layer-0 GEMM  bufA = x @ W0
    gemm_bf16<0, false><<<gemm_grid, 256, GEMM_SMEM>>>(F_IN, 0, nullptr);
    scan_fuse<<<NBLK, SCAN_BS>>>();
    csr_fill<<<nb_edges, 256>>>();
    // layer 0 aggregate + bias + relu -> bufB
    gcn_gather<1, false><<<gat_blocks, 256>>>(b0);
    // layer 1
    gcn_gather<2, true><<<gat_blocks, 256>>>(nullptr);
    gemm_bf16<1, true><<<gemm_grid, 256, GEMM_SMEM>>>(HID, W1_OFS, b1);
    // layer 2
    gcn_gather<1, true><<<gat_blocks, 256>>>(nullptr);
    gemm_bf16<1, true><<<gemm_grid, 256, GEMM_SMEM>>>(HID, W2_OFS, b2);
    // mean pool
    zero_pool<<<(N_GRAPHS * HID + 255) / 256, 256>>>();
    pool_cnt<<<(N_NODES + 255) / 256, 256>>>();
    pool_run<<<(N_NODES + 31) / 32, HID>>>();
    pool_div<<<(N_GRAPHS * HID + 255) / 256, 256>>>();
    // MLP head
    mlp_head<<<N_GRAPHS, HID>>>(Wm1, bm1, Wm2, bm2, out);
}

// round 11
// speedup vs baseline: 2.0893x; 1.0075x over previous
#include <cuda_runtime.h>
#include <cuda_bf16.h>
#include <cuda_pipeline.h>
#include <mma.h>
using namespace nvcuda;

#define N_NODES 50000
#define N_EDGES 800000
#define N_GRAPHS 512
#define F_IN 128
#define HID 256
#define M_PAD 50048                 // 391 * 128
#define SCAN_BS 1024
#define NBLK ((N_NODES + SCAN_BS - 1) / SCAN_BS)   // 49

#define W1_OFS (F_IN * HID)               // 32768
#define W2_OFS (W1_OFS + HID * HID)       // 98304
#define W_TOT  (W2_OFS + HID * HID)       // 163840
#define X_TOT  (N_NODES * F_IN)           // 6400000

// ---------------- scratch (device globals, zero-initialized) ----------------
__device__ int   g_src[N_EDGES];
__device__ int   g_dst[N_EDGES];
__device__ int   g_batch[N_NODES];
__device__ int   g_deg[N_NODES];
__device__ int   g_fill[N_NODES];
__device__ int   g_rowptr[N_NODES + 1];
__device__ int   g_eidx[N_EDGES];
__device__ int   g_blksum[64];
__device__ float g_dis[N_NODES];
__device__ __nv_bfloat16 g_xh[(size_t)M_PAD * F_IN];
__device__ __nv_bfloat16 g_xl[(size_t)M_PAD * F_IN];
__device__ __nv_bfloat16 g_wh[W_TOT];   // W [K][N] row-major, hi
__device__ __nv_bfloat16 g_wl[W_TOT];   // lo
__device__ __nv_bfloat16 g_aggh[(size_t)M_PAD * HID];
__device__ __nv_bfloat16 g_aggl[(size_t)M_PAD * HID];
__device__ float g_bufA[(size_t)M_PAD * HID];   // gemm out
__device__ float g_bufB[(size_t)M_PAD * HID];   // gather0 out
__device__ float g_pool[N_GRAPHS * HID];
__device__ float g_cnt[N_GRAPHS];

// ---------------- setup ----------------
__device__ __forceinline__ void bf16_split(float f, __nv_bfloat16& h, __nv_bfloat16& l) {
    h = __float2bfloat16(f);
    l = __float2bfloat16(f - __bfloat162float(h));
}

__global__ void convert_all(const void* __restrict__ ei, const void* __restrict__ bt,
                            const float* __restrict__ W0, const float* __restrict__ W1,
                            const float* __restrict__ W2, const float* __restrict__ x) {
    int i = blockIdx.x * blockDim.x + threadIdx.x;
    __shared__ int s64;
    if (i - threadIdx.x < N_EDGES) {
        if (threadIdx.x == 0) {
            const unsigned int* raw = (const unsigned int*)ei;
            int all_zero = 1;
            for (int k = 0; k < 64; k++)
                if (raw[2 * k + 1] != 0u) { all_zero = 0; break; }
            s64 = all_zero;
        }
        __syncthreads();
    }
    if (i < N_EDGES) {
        if (s64) {
            const long long* p = (const long long*)ei;
            g_src[i] = (int)p[i];
            g_dst[i] = (int)p[i + N_EDGES];
        } else {
            const int* p = (const int*)ei;
            g_src[i] = p[i];
            g_dst[i] = p[i + N_EDGES];
        }
    }
    if (i < N_NODES) {
        g_batch[i] = s64 ? (int)((const long long*)bt)[i] : ((const int*)bt)[i];
        g_deg[i] = 0;
        g_fill[i] = 0;
    }
    if (i < W_TOT) {
        float w;
        if (i < W1_OFS)      w = W0[i];
        else if (i < W2_OFS) w = W1[i - W1_OFS];
        else                 w = W2[i - W2_OFS];
        bf16_split(w, g_wh[i], g_wl[i]);
    }
    if (i < X_TOT) bf16_split(x[i], g_xh[i], g_xl[i]);
}

// ---------------- CSR construction ----------------
__global__ void deg_hist() {
    int i = blockIdx.x * blockDim.x + threadIdx.x;
    if (i < N_EDGES) atomicAdd(&g_deg[g_dst[i]], 1);
}

__global__ void scan_blocks() {
    __shared__ int sh[SCAN_BS];
    int i = blockIdx.x * SCAN_BS + threadIdx.x;
    int v = (i < N_NODES) ? g_deg[i] : 0;
    sh[threadIdx.x] = v;
    __syncthreads();
    for (int off = 1; off < SCAN_BS; off <<= 1) {
        int t = (threadIdx.x >= off) ? sh[threadIdx.x - off] : 0;
        __syncthreads();
        sh[threadIdx.x] += t;
        __syncthreads();
    }
    if (i < N_NODES) g_rowptr[i] = sh[threadIdx.x] - v;
    if (threadIdx.x == SCAN_BS - 1) g_blksum[blockIdx.x] = sh[threadIdx.x];
}

__global__ void scan_fuse() {
    __shared__ int off;
    if (threadIdx.x == 0) {
        int s = 0;
        for (int b = 0; b < (int)blockIdx.x; b++) s += g_blksum[b];
        off = s;
    }
    __syncthreads();
    int i = blockIdx.x * SCAN_BS + threadIdx.x;
    if (i < N_NODES) {
        g_rowptr[i] += off;
        g_dis[i] = rsqrtf((float)g_deg[i] + 1.f);
    }
    if (i == 0) g_rowptr[N_NODES] = N_EDGES;
}

__global__ void csr_fill() {
    int e = blockIdx.x * blockDim.x + threadIdx.x;
    if (e >= N_EDGES) return;
    int d = g_dst[e];
    int pos = g_rowptr[d] + atomicAdd(&g_fill[d], 1);
    g_eidx[pos] = g_src[e];
}

// ---------------- bf16-split wmma GEMM, block 128x256, warp tile 64x64 ----------------
// g_bufA[M_PAD,256] = A[M_PAD,K] @ W[K,256] (+ bias, relu)
#define BM 128
#define BN 256
#define BK 32
#define LDAS 40
#define LDBS 264
#define A_ELE (BM * LDAS)                  // 5120
#define B_ELE (BK * LDBS)                  // 8448
#define STAGE_ELE (2 * A_ELE + 2 * B_ELE)  // 27136 bf16 = 54272 B
#define SBIAS_OFS (2 * STAGE_ELE * 2)      // 108544 B
#define GEMM_SMEM (SBIAS_OFS + 16 * LDBS * 4)   // + 16896 = 125440 B

template <int ASEL, bool BIASRELU>
__global__ __launch_bounds__(256) void gemm_bf16(int K, int wofs,
                                                 const float* __restrict__ bias) {
    extern __shared__ __align__(16) unsigned char dynsmem[];
    __nv_bfloat16* sm = (__nv_bfloat16*)dynsmem;
    float* sbias = (float*)(dynsmem + SBIAS_OFS);

    const __nv_bfloat16* Ah = ASEL ? g_aggh : g_xh;
    const __nv_bfloat16* Al = ASEL ? g_aggl : g_xl;
    const __nv_bfloat16* Bh = g_wh + wofs;
    const __nv_bfloat16* Bl = g_wl + wofs;

    int bm = blockIdx.y * BM;
    int tid = threadIdx.x;
    int wid = tid >> 5;
    int wm = (wid >> 2) * 64;     // 0/64
    int wn = (wid & 3) * 64;      // 0/64/128/192

    if (BIASRELU) {
        for (int idx = tid; idx < 16 * 256; idx += 256)
            sbias[(idx >> 8) * LDBS + (idx & 255)] = bias[idx & 255];
    }

    const int niter = K / BK;

    auto issue_stage = [&](int it, int s) {
        __nv_bfloat16* Ash = sm + s * STAGE_ELE;
        __nv_bfloat16* Asl = Ash + A_ELE;
        __nv_bfloat16* Bsh = Asl + A_ELE;
        __nv_bfloat16* Bsl = Bsh + B_ELE;
        int k0 = it * BK;
        // A: 128 rows x 32 k = 512 x 16B chunks per buffer
#pragma unroll
        for (int t = 0; t < 2; t++) {
            int id = tid + t * 256;
            int r = id >> 2, q = id & 3;
            const __nv_bfloat16* sh = Ah + (size_t)(bm + r) * K + k0 + q * 8;
            const __nv_bfloat16* sl = Al + (size_t)(bm + r) * K + k0 + q * 8;
            __pipeline_memcpy_async(&Ash[r * LDAS + q * 8], sh, 16);
            __pipeline_memcpy_async(&Asl[r * LDAS + q * 8], sl, 16);
        }
        // B: 32 k x 256 n = 1024 x 16B chunks per buffer
#pragma unroll
        for (int t = 0; t < 4; t++) {
            int id = tid + t * 256;
            int kk = id >> 5, q = id & 31;
            const __nv_bfloat16* sh = Bh + (size_t)(k0 + kk) * HID + q * 8;
            const __nv_bfloat16* sl = Bl + (size_t)(k0 + kk) * HID + q * 8;
            __pipeline_memcpy_async(&Bsh[kk * LDBS + q * 8], sh, 16);
            __pipeline_memcpy_async(&Bsl[kk * LDBS + q * 8], sl, 16);
        }
        __pipeline_commit();
    };

    wmma::fragment<wmma::accumulator, 16, 16, 16, float> acc[4][4];
#pragma unroll
    for (int i = 0; i < 4; i++)
#pragma unroll
        for (int j = 0; j < 4; j++) wmma::fill_fragment(acc[i][j], 0.f);

    issue_stage(0, 0);

    for (int it = 0; it < niter; it++) {
        if (it + 1 < niter) issue_stage(it + 1, (it + 1) & 1);
        __pipeline_wait_prior((it + 1 < niter) ? 1 : 0);
        __syncthreads();

        __nv_bfloat16* Ash = sm + (it & 1) * STAGE_ELE;
        __nv_bfloat16* Asl = Ash + A_ELE;
        __nv_bfloat16* Bsh = Asl + A_ELE;
        __nv_bfloat16* Bsl = Bsh + B_ELE;

#pragma unroll
        for (int ks = 0; ks < 2; ks++) {
            wmma::fragment<wmma::matrix_a, 16, 16, 16, __nv_bfloat16, wmma::row_major> ah[4], al[4];
#pragma unroll
            for (int i = 0; i < 4; i++) {
                wmma::load_matrix_sync(ah[i], Ash + (wm + i * 16) * LDAS + ks * 16, LDAS);
                wmma::load_matrix_sync(al[i], Asl + (wm + i * 16) * LDAS + ks * 16, LDAS);
            }
#pragma unroll
            for (int j = 0; j < 4; j++) {
                wmma::fragment<wmma::matrix_b, 16, 16, 16, __nv_bfloat16, wmma::row_major> bh, bl;
                wmma::load_matrix_sync(bh, Bsh + (ks * 16) * LDBS + wn + j * 16, LDBS);
                wmma::load_matrix_sync(bl, Bsl + (ks * 16) * LDBS + wn + j * 16, LDBS);
#pragma unroll
                for (int i = 0; i < 4; i++) {
                    wmma::mma_sync(acc[i][j], ah[i], bh, acc[i][j]);
                    wmma::mma_sync(acc[i][j], ah[i], bl, acc[i][j]);
                    wmma::mma_sync(acc[i][j], al[i], bh, acc[i][j]);
                }
            }
        }
        __syncthreads();
    }

    // epilogue: bias + relu via layout-matched fragment, direct global store
#pragma unroll
    for (int i = 0; i < 4; i++)
#pragma unroll
        for (int j = 0; j < 4; j++) {
            if (BIASRELU) {
                wmma::fragment<wmma::accumulator, 16, 16, 16, float> bf;
                wmma::load_matrix_sync(bf, sbias + wn + j * 16, LDBS, wmma::mem_row_major);
#pragma unroll
                for (int e = 0; e < acc[i][j].num_elements; e++)
                    acc[i][j].x[e] = fmaxf(acc[i][j].x[e] + bf.x[e], 0.f);
            }
            wmma::store_matrix_sync(g_bufA + (size_t)(bm + wm + i * 16) * HID + wn + j * 16,
                                    acc[i][j], HID, wmma::mem_row_major);
        }
}

// ---------------- gather: warp per node ----------------
template <int SRC, bool SPLIT>
__global__ void gcn_gather(const float* __restrict__ bias) {
    int node = (blockIdx.x * blockDim.x + threadIdx.x) >> 5;
    int lane = threadIdx.x & 31;
    if (node >= N_NODES) return;

    const float* hsrc = (SRC == 1) ? (const float*)g_bufA : (const float*)g_bufB;

    float di = g_dis[node];
    float dd = di * di;
    const float4* hn = (const float4*)(hsrc + (size_t)node * HID);

    float4 acc[2];
#pragma unroll
    for (int v = 0; v < 2; v++) {
        float4 a = hn[lane + 32 * v];
        acc[v] = make_float4(a.x * dd, a.y * dd, a.z * dd, a.w * dd);
    }

    int beg = g_rowptr[node], end = g_rowptr[node + 1];
    for (int e = beg; e < end; e++) {
        int s = g_eidx[e];
        float nrm = g_dis[s] * di;
        const float4* hs = (const float4*)(hsrc + (size_t)s * HID);
#pragma unroll
        for (int v = 0; v < 2; v++) {
            float4 x = hs[lane + 32 * v];
            acc[v].x = fmaf(x.x, nrm, acc[v].x);
            acc[v].y = fmaf(x.y, nrm, acc[v].y);
            acc[v].z = fmaf(x.z, nrm, acc[v].z);
            acc[v].w = fmaf(x.w, nrm, acc[v].w);
        }
    }

    if (SPLIT) {
#pragma unroll
        for (int v = 0; v < 2; v++) {
            __nv_bfloat162 h01, h23, l01, l23;
            bf16_split(acc[v].x, h01.x, l01.x);
            bf16_split(acc[v].y, h01.y, l01.y);
            bf16_split(acc[v].z, h23.x, l23.x);
            bf16_split(acc[v].w, h23.y, l23.y);
            uint2 uh = make_uint2(*(unsigned*)&h01, *(unsigned*)&h23);
            uint2 ul = make_uint2(*(unsigned*)&l01, *(unsigned*)&l23);
            ((uint2*)(g_aggh + (size_t)node * HID))[lane + 32 * v] = uh;
            ((uint2*)(g_aggl + (size_t)node * HID))[lane + 32 * v] = ul;
        }
    } else {
        const float4* bi = (const float4*)bias;
        float4* ob = (float4*)(g_bufB + (size_t)node * HID);
#pragma unroll
        for (int v = 0; v < 2; v++) {
            float4 b = bi[lane + 32 * v];
            float4 r;
            r.x = fmaxf(acc[v].x + b.x, 0.f);
            r.y = fmaxf(acc[v].y + b.y, 0.f);
            r.z = fmaxf(acc[v].z + b.z, 0.f);
            r.w = fmaxf(acc[v].w + b.w, 0.f);
            ob[lane + 32 * v] = r;
        }
    }
}

// ---------------- pooling ----------------
__global__ void zero_pool() {
    int i = blockIdx.x * blockDim.x + threadIdx.x;
    if (i < N_GRAPHS * HID) g_pool[i] = 0.f;
    if (i < N_GRAPHS) g_cnt[i] = 0.f;
}

__global__ void pool_cnt() {
    int i = blockIdx.x * blockDim.x + threadIdx.x;
    if (i < N_NODES) atomicAdd(&g_cnt[g_batch[i]], 1.f);
}

__global__ void pool_run() {
    int c = threadIdx.x;
    int base = blockIdx.x * 32;
    float run = 0.f;
    int cur = -1;
    for (int r = 0; r < 32; r++) {
        int node = base + r;
        if (node >= N_NODES) break;
        int b = g_batch[node];
        if (b != cur) {
            if (cur >= 0) atomicAdd(&g_pool[cur * HID + c], run);
            run = 0.f;
            cur = b;
        }
        run += g_bufA[(size_t)node * HID + c];
    }
    if (cur >= 0) atomicAdd(&g_pool[cur * HID + c], run);
}

__global__ void pool_div() {
    int i = blockIdx.x * blockDim.x + threadIdx.x;
    if (i < N_GRAPHS * HID) g_pool[i] /= fmaxf(g_cnt[i >> 8], 1.f);
}

// ---------------- fused MLP head ----------------
__global__ void mlp_head(const float* __restrict__ Wm1, const float* __restrict__ bm1,
                         const float* __restrict__ Wm2, const float* __restrict__ bm2,
                         float* __restrict__ out) {
    int g = blockIdx.x;
    int c = threadIdx.x;
    __shared__ float p[HID];
    __shared__ float z[HID];
    p[c] = g_pool[g * HID + c];
    __syncthreads();
    float acc = bm1[c];
#pragma unroll 8
    for (int k = 0; k < HID; k++) acc = fmaf(p[k], Wm1[k * HID + c], acc);
    z[c] = fmaxf(acc, 0.f) * Wm2[c];
    __syncthreads();
    for (int s = 128; s > 0; s >>= 1) {
        if (c < s) z[c] += z[c + s];
        __syncthreads();
    }
    if (c == 0) out[g] = z[0] + bm2[0];
}

// ---------------- launcher ----------------
extern "C" void kernel_launch(void* const* d_in, const int* in_sizes, int n_in,
                              void* d_out, int out_size) {
    const float* x   = (const float*)d_in[0];
    const void*  ei  = d_in[1];
    const void*  bt  = d_in[2];
    const float* W0  = (const float*)d_in[3];
    const float* b0  = (const float*)d_in[4];
    const float* W1  = (const float*)d_in[5];
    const float* b1  = (const float*)d_in[6];
    const float* W2  = (const float*)d_in[7];
    const float* b2  = (const float*)d_in[8];
    const float* Wm1 = (const float*)d_in[9];
    const float* bm1 = (const float*)d_in[10];
    const float* Wm2 = (const float*)d_in[11];
    const float* bm2 = (const float*)d_in[12];
    float* out = (float*)d_out;

    cudaFuncSetAttribute(gemm_bf16<0, false>, cudaFuncAttributeMaxDynamicSharedMemorySize, GEMM_SMEM);
    cudaFuncSetAttribute(gemm_bf16<1, true>,  cudaFuncAttributeMaxDynamicSharedMemorySize, GEMM_SMEM);

    const int nb_edges = (N_EDGES + 255) / 256;
    const int cvt_blocks = (X_TOT + 255) / 256;
    const int gat_blocks = (N_NODES * 32 + 255) / 256;
    dim3 gemm_grid(1, M_PAD / BM);                  // (1, 391)

    convert_all<<<cvt_blocks, 256>>>(ei, bt, W0, W1, W2, x);
    deg_hist<<<nb_edges, 256>>>();
    scan_blocks<<<NBLK, SCAN_BS>>>();
    // launch 3 (profiled): layer-0 GEMM  bufA = x @ W0
    gemm_bf16<0, false><<<gemm_grid, 256, GEMM_SMEM>>>(F_IN, 0, nullptr);
    scan_fuse<<<NBLK, SCAN_BS>>>();
    csr_fill<<<nb_edges, 256>>>();
    // layer 0 aggregate + bias + relu -> bufB
    gcn_gather<1, false><<<gat_blocks, 256>>>(b0);
    // layer 1
    gcn_gather<2, true><<<gat_blocks, 256>>>(nullptr);
    gemm_bf16<1, true><<<gemm_grid, 256, GEMM_SMEM>>>(HID, W1_OFS, b1);
    // layer 2
    gcn_gather<1, true><<<gat_blocks, 256>>>(nullptr);
    gemm_bf16<1, true><<<gemm_grid, 256, GEMM_SMEM>>>(HID, W2_OFS, b2);
    // mean pool
    zero_pool<<<(N_GRAPHS * HID + 255) / 256, 256>>>();
    pool_cnt<<<(N_NODES + 255) / 256, 256>>>();
    pool_run<<<(N_NODES + 31) / 32, HID>>>();
    pool_div<<<(N_GRAPHS * HID + 255) / 256, 256>>>();
    // MLP head
    mlp_head<<<N_GRAPHS, HID>>>(Wm1, bm1, Wm2, bm2, out);
}